// round 14
// baseline (speedup 1.0000x reference)
#include <cuda_runtime.h>
#include <math_constants.h>

// Problem constants
#define B 32
#define Q 10000
#define C 80
#define TOPK 200
#define NW 7                   // 224 bits >= 200

// K1 tiling
#define ROWS 128               // queries per block
#define RPAD 21                // row stride in float4 units (odd -> conflict-free LDS)
#define NF4 20                 // 80 floats = 20 float4 per row

// K2
#define KTHREADS 512
#define CANDCAP 1024
#define CLSCAP 16              // per-class candidate cap (avg is 2.5)

// Histogram (score in (0,1] -> bits in (0x3C4CCCCD .. 0x3F800000])
#define HBASE 0x3C000000u
#define HSHIFT 14
#define NBKT 3584              // (0x3F800000 - 0x3C000000) >> 14
#define BPT 7                  // buckets per thread (7 * 512 = 3584)

// Scratch
__device__ unsigned int g_score[B * Q];
__device__ unsigned int g_hist[B * NBKT];   // zero-init at load; K2 re-zeroes each launch

// ---------------------------------------------------------------------------
// K1: thread-per-query score (bitwise identical arithmetic to all passing
// rounds) + per-batch histogram of score bits (REDG, no return needed).
// ---------------------------------------------------------------------------
__global__ __launch_bounds__(ROWS) void score_kernel(const float* __restrict__ logits) {
    __shared__ float4 s[ROWS * RPAD];          // 43008 B
    int tid = threadIdx.x;

    const float4* gin = (const float4*)logits + (size_t)blockIdx.x * (ROWS * NF4);
    #pragma unroll
    for (int it = 0; it < NF4; it++) {
        int fi = it * ROWS + tid;
        int r = fi / NF4, c = fi % NF4;
        s[r * RPAD + c] = gin[fi];
    }
    __syncthreads();

    const float4* row = s + tid * RPAD;

    float m = -CUDART_INF_F;
    #pragma unroll
    for (int j = 0; j < NF4; j++) {
        float4 f = row[j];
        m = fmaxf(m, fmaxf(fmaxf(f.x, f.y), fmaxf(f.z, f.w)));
    }

    float ep[32];
    #pragma unroll
    for (int l = 0; l < 32; l++) ep[l] = 0.0f;
    #pragma unroll
    for (int j = 0; j < NF4; j++) {
        float4 f = row[j];
        ep[(4 * j + 0) & 31] += expf(f.x - m);
        ep[(4 * j + 1) & 31] += expf(f.y - m);
        ep[(4 * j + 2) & 31] += expf(f.z - m);
        ep[(4 * j + 3) & 31] += expf(f.w - m);
    }
    float e1[32], e2[32], e3[32], e4[32];
    #pragma unroll
    for (int l = 0; l < 32; l++) e1[l] = ep[l] + ep[l ^ 16];
    #pragma unroll
    for (int l = 0; l < 32; l++) e2[l] = e1[l] + e1[l ^ 8];
    #pragma unroll
    for (int l = 0; l < 32; l++) e3[l] = e2[l] + e2[l ^ 4];
    #pragma unroll
    for (int l = 0; l < 32; l++) e4[l] = e3[l] + e3[l ^ 2];
    float e = e4[0] + e4[1];

    float score = 1.0f / e;                    // in [1/80, 1]
    unsigned int bits = __float_as_uint(score);
    int gq = blockIdx.x * ROWS + tid;
    g_score[gq] = bits;

    int bb = gq / Q;
    int bk = (int)((bits - HBASE) >> HSHIFT);
    if (bk > NBKT - 1) bk = NBKT - 1;
    atomicAdd(&g_hist[bb * NBKT + bk], 1u);
}

// ---------------------------------------------------------------------------
// K2 (fused, per batch, 512 threads): histogram cutoff (1 scan, no search
// rounds) -> compaction -> guarded rank-by-counting -> single-wave argmax ->
// per-class NMS -> float output.
// ---------------------------------------------------------------------------
__global__ __launch_bounds__(KTHREADS) void select_nms_kernel(const float* __restrict__ logits,
                                                              const float* __restrict__ seg,
                                                              float* __restrict__ out) {
    __shared__ unsigned int s_w[16];
    __shared__ int s_cut, s_cnt, s_ovf;
    __shared__ unsigned long long ck[CANDCAP];  // 8 KB
    __shared__ float sx1[TOPK], sx2[TOPK];
    __shared__ int   sq[TOPK];
    __shared__ unsigned char scls8[(TOPK + 3) & ~3];
    __shared__ unsigned char sact200[TOPK];
    __shared__ unsigned int sact[NW], spre[NW];

    int b = blockIdx.x;
    int t = threadIdx.x;
    int lane = t & 31, wid = t >> 5;
    const unsigned int* sc = g_score + b * Q;

    if (t == 0) { s_cut = 0; s_cnt = 0; s_ovf = 0; }
    // init output early
    if (t < TOPK) {
        out[b * TOPK + t]       = -1.0f;
        out[(B + b) * TOPK + t] = 0.0f;
    }

    // ---- histogram cutoff: largest bucket c with suffix-count >= TOPK ----
    unsigned int h[BPT];
    int bket0 = t * BPT;
    unsigned int p = 0;
    #pragma unroll
    for (int k = 0; k < BPT; k++) { h[k] = g_hist[b * NBKT + bket0 + k]; p += h[k]; }
    // warp inclusive suffix-scan of p (v = sum over lanes >= lane)
    unsigned int v = p;
    #pragma unroll
    for (int o = 1; o < 32; o <<= 1) {
        unsigned int u = __shfl_down_sync(0xffffffffu, v, o);
        if (lane + o < 32) v += u;
    }
    unsigned int wtot = __shfl_sync(0xffffffffu, v, 0);
    if (lane == 0) s_w[wid] = wtot;
    __syncthreads();
    unsigned int wsufx = 0;
    for (int w = wid + 1; w < 16; w++) wsufx += s_w[w];
    unsigned int chunkSuffix = wsufx + v;      // count of scores in buckets >= bket0
    unsigned int pre = 0, best = 0;
    #pragma unroll
    for (int k = 0; k < BPT; k++) {
        unsigned int sfx = chunkSuffix - pre;  // suffix at bucket bket0+k
        if (sfx >= TOPK) best = ((unsigned)(bket0 + k) << 14) | sfx;  // sfx <= 10000 < 2^14
        pre += h[k];
    }
    if (best) atomicMax(&s_cut, (int)best);
    // re-zero histogram slice for next graph replay (deterministic)
    #pragma unroll
    for (int k = 0; k < BPT; k++) g_hist[b * NBKT + bket0 + k] = 0u;
    __syncthreads();
    unsigned int cutp = (unsigned int)s_cut;
    unsigned int thr = HBASE + ((cutp >> 14) << HSHIFT);

    // ---- compaction: scores with bits >= thr (exactly the suffix count) ----
    #pragma unroll
    for (int k = 0; k < 20; k++) {
        int i = k * KTHREADS + t;
        unsigned int bits = (i < Q) ? sc[i] : 0u;
        bool pred = bits >= thr;
        unsigned int mask = __ballot_sync(0xffffffffu, pred);
        if (mask) {
            int leader = __ffs(mask) - 1;
            int base = 0;
            if (lane == leader) base = atomicAdd(&s_cnt, __popc(mask));
            base = __shfl_sync(0xffffffffu, base, leader);
            if (pred) {
                int pos = base + __popc(mask & ((1u << lane) - 1u));
                if (pos < CANDCAP)
                    ck[pos] = ((unsigned long long)bits << 32) |
                              (unsigned int)(~(unsigned int)i);
            }
        }
    }
    __syncthreads();
    int cnt = s_cnt; if (cnt > CANDCAP) cnt = CANDCAP;

    // ---- rank by counting (guarded: only ~cnt threads loop). Keys unique,
    //      so rank(t) = #{j: key_j > key_t} is the descending-sort position. ----
    if (t < cnt) {
        unsigned long long key = ck[t];
        int r = 0;
        int j = 0;
        for (; j + 4 <= cnt; j += 4) {
            r += (ck[j]     > key);
            r += (ck[j + 1] > key);
            r += (ck[j + 2] > key);
            r += (ck[j + 3] > key);
        }
        for (; j < cnt; j++) r += (ck[j] > key);
        if (r < TOPK) {
            int q = (int)(~(unsigned int)key);
            sq[r] = q;
            float2 xy = ((const float2*)seg)[b * Q + q];
            sx1[r] = xy.x; sx2[r] = xy.y;
            sact200[r] = 1;
        }
    }
    __syncthreads();

    // ---- lazy argmax for the 200 winners: single wave, 13 rows/warp in flight
    {
        float a0[13], a1[13], a2[13];
        #pragma unroll
        for (int i = 0; i < 13; i++) {
            int c = wid + i * 16;
            if (c < TOPK) {                     // warp-uniform guard
                const float* pptr = logits + ((size_t)b * Q + sq[c]) * C;
                a0[i] = pptr[lane];
                a1[i] = pptr[32 + lane];
                a2[i] = (lane < 16) ? pptr[64 + lane] : -CUDART_INF_F;
            }
        }
        #pragma unroll
        for (int i = 0; i < 13; i++) {
            int c = wid + i * 16;
            if (c < TOPK) {
                float m = a0[i]; int mi = lane;
                if (a1[i] > m) { m = a1[i]; mi = 32 + lane; }
                if (a2[i] > m) { m = a2[i]; mi = 64 + lane; }
                #pragma unroll
                for (int o = 16; o; o >>= 1) {
                    float om = __shfl_xor_sync(0xffffffffu, m, o);
                    int   oi = __shfl_xor_sync(0xffffffffu, mi, o);
                    if (om > m || (om == m && oi < mi)) { m = om; mi = oi; }
                }
                if (lane == 0) scls8[c] = (unsigned char)mi;
            }
        }
    }
    __syncthreads();

    // ---- per-class greedy NMS (exact decomposition of the global greedy) ----
    if (t < C) {
        int list[CLSCAP]; int n = 0;
        const unsigned int* sc4 = (const unsigned int*)scls8;
        #pragma unroll 5
        for (int w = 0; w < TOPK / 4; w++) {
            unsigned int pk = sc4[w];
            #pragma unroll
            for (int e = 0; e < 4; e++) {
                if (((pk >> (8 * e)) & 0xFFu) == (unsigned)t) {
                    if (n < CLSCAP) list[n] = w * 4 + e;
                    n++;
                }
            }
        }
        if (n > CLSCAP) {
            s_ovf = 1;
        } else {
            unsigned int actm = (1u << n) - 1u;     // n <= 16
            for (int a = 0; a < n; a++) {
                if (actm & (1u << a)) {
                    int ja = list[a];
                    float ax1 = sx1[ja], ax2 = sx2[ja];
                    for (int bb = a + 1; bb < n; bb++) {
                        if (actm & (1u << bb)) {
                            int jb = list[bb];
                            float inter = fminf(sx2[jb], ax2) - fmaxf(sx1[jb], ax1);
                            if (inter > 0.0f) actm &= ~(1u << bb);
                        }
                    }
                }
            }
            for (int bb = 0; bb < n; bb++)
                if (!(actm & (1u << bb))) sact200[list[bb]] = 0;
        }
    }
    __syncthreads();
    if (s_ovf) {                                // exact fallback (never expected)
        if (t == 0) {
            for (int j = 0; j < TOPK; j++) sact200[j] = 1;
            for (int p2 = 0; p2 < TOPK; p2++) {
                if (!sact200[p2]) continue;
                float px1 = sx1[p2], px2 = sx2[p2]; int pc = scls8[p2];
                for (int j = p2 + 1; j < TOPK; j++) {
                    if (sact200[j] && scls8[j] == pc) {
                        float inter = fminf(sx2[j], px2) - fmaxf(sx1[j], px1);
                        if (inter > 0.0f) sact200[j] = 0;
                    }
                }
            }
        }
        __syncthreads();
    }

    // ---- rank kept candidates & write out ----
    if (t < NW * 32) {
        bool pred = (t < TOPK) && (sact200[t] != 0);
        unsigned int m = __ballot_sync(0xffffffffu, pred);
        if (lane == 0) sact[wid] = m;
    }
    __syncthreads();
    if (t == 0) {
        unsigned int c = 0;
        #pragma unroll
        for (int w = 0; w < NW; w++) { spre[w] = c; c += __popc(sact[w]); }
    }
    __syncthreads();
    if (t < TOPK) {
        unsigned int w = (unsigned)t >> 5, bmask = 1u << (t & 31);
        unsigned int aw = sact[w];
        if (aw & bmask) {
            int rank = spre[w] + __popc(aw & (bmask - 1u));
            out[b * TOPK + rank] = (float)sq[t];
        }
    }
}

// ---------------------------------------------------------------------------
extern "C" void kernel_launch(void* const* d_in, const int* in_sizes, int n_in,
                              void* d_out, int out_size) {
    const float* logits = (const float*)d_in[0];   // [B,Q,C] f32
    const float* seg    = (const float*)d_in[1];   // [B,Q,2] f32
    float* out = (float*)d_out;                    // [2B, TOPK] float32 values

    score_kernel<<<(B * Q) / ROWS, ROWS>>>(logits);          // 2500 blocks
    select_nms_kernel<<<B, KTHREADS>>>(logits, seg, out);    // 32 blocks
}

// round 16
// speedup vs baseline: 1.4311x; 1.4311x over previous
#include <cuda_runtime.h>
#include <math_constants.h>

// Problem constants
#define B 32
#define Q 10000
#define C 80
#define TOPK 200
#define NW 7                   // 224 bits >= 200

// K1 tiling
#define ROWS 128               // queries per block
#define RPAD 21                // row stride in float4 units (odd -> conflict-free LDS)
#define NF4 20                 // 80 floats = 20 float4 per row

// K2 selection
#define KTHREADS 512
#define VPT 20                 // scores per thread (20 * 512 >= Q)
#define CANDCAP 512
#define LO_BITS 0x3C000000u    // < bits(1/80): every score exceeds this
#define HI_BITS 0x3F800001u    // > bits(1.0)
#define MAXROUNDS 20
#define CLSCAP 16              // per-class candidate cap (avg is 2.5)

// Scratch: scores only (class is computed lazily for selected candidates)
__device__ unsigned int g_score[B * Q];

// ---------------------------------------------------------------------------
// K1: thread-per-query score (bitwise identical to all passing rounds).
// ---------------------------------------------------------------------------
__global__ __launch_bounds__(ROWS) void score_kernel(const float* __restrict__ logits) {
    __shared__ float4 s[ROWS * RPAD];          // 43008 B
    int tid = threadIdx.x;

    const float4* gin = (const float4*)logits + (size_t)blockIdx.x * (ROWS * NF4);
    #pragma unroll
    for (int it = 0; it < NF4; it++) {
        int fi = it * ROWS + tid;
        int r = fi / NF4, c = fi % NF4;
        s[r * RPAD + c] = gin[fi];
    }
    __syncthreads();

    const float4* row = s + tid * RPAD;

    float m = -CUDART_INF_F;
    #pragma unroll
    for (int j = 0; j < NF4; j++) {
        float4 f = row[j];
        m = fmaxf(m, fmaxf(fmaxf(f.x, f.y), fmaxf(f.z, f.w)));
    }

    float ep[32];
    #pragma unroll
    for (int l = 0; l < 32; l++) ep[l] = 0.0f;
    #pragma unroll
    for (int j = 0; j < NF4; j++) {
        float4 f = row[j];
        ep[(4 * j + 0) & 31] += expf(f.x - m);
        ep[(4 * j + 1) & 31] += expf(f.y - m);
        ep[(4 * j + 2) & 31] += expf(f.z - m);
        ep[(4 * j + 3) & 31] += expf(f.w - m);
    }
    float e1[32], e2[32], e3[32], e4[32];
    #pragma unroll
    for (int l = 0; l < 32; l++) e1[l] = ep[l] + ep[l ^ 16];
    #pragma unroll
    for (int l = 0; l < 32; l++) e2[l] = e1[l] + e1[l ^ 8];
    #pragma unroll
    for (int l = 0; l < 32; l++) e3[l] = e2[l] + e2[l ^ 4];
    #pragma unroll
    for (int l = 0; l < 32; l++) e4[l] = e3[l] + e3[l ^ 2];
    float e = e4[0] + e4[1];

    float score = 1.0f / e;
    g_score[(size_t)blockIdx.x * ROWS + tid] = __float_as_uint(score);
}

// ---------------------------------------------------------------------------
// K2 (fused, per batch, 512 threads): tri-section threshold -> compaction ->
// GUARDED rank-by-counting (replaces bitonic sort) -> single-wave argmax ->
// per-class NMS -> float output.   (All stages except ranking are the
// validated R11 configuration.)
// ---------------------------------------------------------------------------
__global__ __launch_bounds__(KTHREADS) void select_nms_kernel(const float* __restrict__ logits,
                                                              const float* __restrict__ seg,
                                                              float* __restrict__ out) {
    __shared__ unsigned int s_tot[MAXROUNDS];
    __shared__ int s_cnt;
    __shared__ unsigned long long ck[CANDCAP];  // 4 KB
    __shared__ float sx1[TOPK], sx2[TOPK];
    __shared__ int   sq[TOPK];
    __shared__ unsigned char scls8[(TOPK + 3) & ~3];
    __shared__ unsigned char sact200[TOPK];
    __shared__ int s_ovf;
    __shared__ unsigned int sact[NW], spre[NW];

    int b = blockIdx.x;
    int t = threadIdx.x;
    int lane = t & 31, wid = t >> 5;
    const unsigned int* sc = g_score + b * Q;

    // ---- load scores into registers (coalesced; pads = 0) ----
    unsigned int v[VPT];
    #pragma unroll
    for (int k = 0; k < VPT; k++) {
        int i = k * KTHREADS + t;
        v[k] = (i < Q) ? sc[i] : 0u;
    }
    if (t < MAXROUNDS) s_tot[t] = 0u;
    if (t == 0) { s_cnt = 0; s_ovf = 0; }
    // init output early (overlaps with threshold search)
    if (t < TOPK) {
        out[b * TOPK + t]       = -1.0f;
        out[(B + b) * TOPK + t] = 0.0f;
    }
    __syncthreads();

    // ---- tri-section: largest thr with count(>=thr) >= TOPK, stop at <=CANDCAP
    unsigned int lo = LO_BITS, hi = HI_BITS;
    int cntlo = Q;
    for (int r = 0; r < MAXROUNDS; r++) {
        if (cntlo <= CANDCAP) break;
        unsigned int d = (hi - lo) / 3u;
        if (d == 0) break;
        unsigned int m1 = lo + d, m2 = lo + 2u * d;
        unsigned int c1 = 0, c2 = 0;
        #pragma unroll
        for (int k = 0; k < VPT; k++) { c1 += (v[k] >= m1); c2 += (v[k] >= m2); }
        unsigned int packed = (c1 << 16) | c2;
        unsigned int wsum = __reduce_add_sync(0xffffffffu, packed);
        if (lane == 0) atomicAdd(&s_tot[r], wsum);
        __syncthreads();
        unsigned int tot = s_tot[r];
        int tc1 = (int)(tot >> 16), tc2 = (int)(tot & 0xFFFFu);
        if (tc2 >= TOPK)      { lo = m2; cntlo = tc2; }
        else if (tc1 >= TOPK) { lo = m1; cntlo = tc1; hi = m2; }
        else                  { hi = m1; }
    }
    unsigned int thr = lo;

    // ---- compact candidates (warp-aggregated; order fixed by ranking) ----
    #pragma unroll
    for (int k = 0; k < VPT; k++) {
        int i = k * KTHREADS + t;
        bool pred = (i < Q) && (v[k] >= thr);
        unsigned int mask = __ballot_sync(0xffffffffu, pred);
        if (mask) {
            int leader = __ffs(mask) - 1;
            int base = 0;
            if (lane == leader) base = atomicAdd(&s_cnt, __popc(mask));
            base = __shfl_sync(0xffffffffu, base, leader);
            if (pred) {
                int pos = base + __popc(mask & ((1u << lane) - 1u));
                if (pos < CANDCAP)
                    ck[pos] = ((unsigned long long)v[k] << 32) |
                              (unsigned int)(~(unsigned int)i);
            }
        }
    }
    __syncthreads();
    int cnt = s_cnt; if (cnt > CANDCAP) cnt = CANDCAP;

    // ---- rank by counting (GUARDED: only cnt threads loop; keys unique so
    //      rank(t) = #{j: key_j > key_t} is the descending-sort position;
    //      all TOPK slots are filled because cnt >= TOPK by construction). ----
    if (t < cnt) {
        unsigned long long key = ck[t];
        int r = 0;
        int j = 0;
        for (; j + 8 <= cnt; j += 8) {
            r += (ck[j]     > key);
            r += (ck[j + 1] > key);
            r += (ck[j + 2] > key);
            r += (ck[j + 3] > key);
            r += (ck[j + 4] > key);
            r += (ck[j + 5] > key);
            r += (ck[j + 6] > key);
            r += (ck[j + 7] > key);
        }
        for (; j < cnt; j++) r += (ck[j] > key);
        if (r < TOPK) {
            int q = (int)(~(unsigned int)key);
            sq[r] = q;
            float2 xy = ((const float2*)seg)[b * Q + q];
            sx1[r] = xy.x; sx2[r] = xy.y;
            sact200[r] = 1;
        }
    }
    __syncthreads();

    // ---- lazy argmax for the 200 winners: single wave, 13 rows/warp in flight
    {
        float a0[13], a1[13], a2[13];
        #pragma unroll
        for (int i = 0; i < 13; i++) {
            int c = wid + i * 16;
            if (c < TOPK) {                     // warp-uniform guard
                const float* pptr = logits + ((size_t)b * Q + sq[c]) * C;
                a0[i] = pptr[lane];
                a1[i] = pptr[32 + lane];
                a2[i] = (lane < 16) ? pptr[64 + lane] : -CUDART_INF_F;
            }
        }
        #pragma unroll
        for (int i = 0; i < 13; i++) {
            int c = wid + i * 16;
            if (c < TOPK) {
                float m = a0[i]; int mi = lane;
                if (a1[i] > m) { m = a1[i]; mi = 32 + lane; }
                if (a2[i] > m) { m = a2[i]; mi = 64 + lane; }
                #pragma unroll
                for (int o = 16; o; o >>= 1) {
                    float om = __shfl_xor_sync(0xffffffffu, m, o);
                    int   oi = __shfl_xor_sync(0xffffffffu, mi, o);
                    if (om > m || (om == m && oi < mi)) { m = om; mi = oi; }
                }
                if (lane == 0) scls8[c] = (unsigned char)mi;
            }
        }
    }
    __syncthreads();

    // ---- per-class greedy NMS (exact decomposition of the global greedy) ----
    if (t < C) {
        int list[CLSCAP]; int n = 0;
        const unsigned int* sc4 = (const unsigned int*)scls8;
        #pragma unroll 5
        for (int w = 0; w < TOPK / 4; w++) {
            unsigned int pk = sc4[w];
            #pragma unroll
            for (int e = 0; e < 4; e++) {
                if (((pk >> (8 * e)) & 0xFFu) == (unsigned)t) {
                    if (n < CLSCAP) list[n] = w * 4 + e;
                    n++;
                }
            }
        }
        if (n > CLSCAP) {
            s_ovf = 1;
        } else {
            unsigned int actm = (1u << n) - 1u;     // n <= 16
            for (int a = 0; a < n; a++) {
                if (actm & (1u << a)) {
                    int ja = list[a];
                    float ax1 = sx1[ja], ax2 = sx2[ja];
                    for (int bb = a + 1; bb < n; bb++) {
                        if (actm & (1u << bb)) {
                            int jb = list[bb];
                            float inter = fminf(sx2[jb], ax2) - fmaxf(sx1[jb], ax1);
                            if (inter > 0.0f) actm &= ~(1u << bb);
                        }
                    }
                }
            }
            for (int bb = 0; bb < n; bb++)
                if (!(actm & (1u << bb))) sact200[list[bb]] = 0;
        }
    }
    __syncthreads();
    if (s_ovf) {                                // exact fallback (never expected)
        if (t == 0) {
            for (int j = 0; j < TOPK; j++) sact200[j] = 1;
            for (int p2 = 0; p2 < TOPK; p2++) {
                if (!sact200[p2]) continue;
                float px1 = sx1[p2], px2 = sx2[p2]; int pc = scls8[p2];
                for (int j = p2 + 1; j < TOPK; j++) {
                    if (sact200[j] && scls8[j] == pc) {
                        float inter = fminf(sx2[j], px2) - fmaxf(sx1[j], px1);
                        if (inter > 0.0f) sact200[j] = 0;
                    }
                }
            }
        }
        __syncthreads();
    }

    // ---- rank kept candidates & write out ----
    if (t < NW * 32) {
        bool pred = (t < TOPK) && (sact200[t] != 0);
        unsigned int m = __ballot_sync(0xffffffffu, pred);
        if (lane == 0) sact[wid] = m;
    }
    __syncthreads();
    if (t == 0) {
        unsigned int c = 0;
        #pragma unroll
        for (int w = 0; w < NW; w++) { spre[w] = c; c += __popc(sact[w]); }
    }
    __syncthreads();
    if (t < TOPK) {
        unsigned int w = (unsigned)t >> 5, bmask = 1u << (t & 31);
        unsigned int aw = sact[w];
        if (aw & bmask) {
            int rank = spre[w] + __popc(aw & (bmask - 1u));
            out[b * TOPK + rank] = (float)sq[t];
        }
    }
}

// ---------------------------------------------------------------------------
extern "C" void kernel_launch(void* const* d_in, const int* in_sizes, int n_in,
                              void* d_out, int out_size) {
    const float* logits = (const float*)d_in[0];   // [B,Q,C] f32
    const float* seg    = (const float*)d_in[1];   // [B,Q,2] f32
    float* out = (float*)d_out;                    // [2B, TOPK] float32 values

    score_kernel<<<(B * Q) / ROWS, ROWS>>>(logits);          // 2500 blocks
    select_nms_kernel<<<B, KTHREADS>>>(logits, seg, out);    // 32 blocks
}